// round 14
// baseline (speedup 1.0000x reference)
#include <cuda_runtime.h>
#include <cuda_bf16.h>

#define HID 32
#define CUTOFF_SQ 6.25f
#define THREADS 256
#define TBL 2048
#define NMAX 4096
#define NCELL 5
#define NCELLS (NCELL * NCELL * NCELL)   // 125

__device__ float  g_tbl[TBL + 1];        // 0.5 * e(sqrt(u)), u = r^2
__device__ float4 g_tmp[NMAX];           // unsorted positions
__device__ float4 g_sorted[NMAX];        // cell-sorted positions, .w = cell id bits
__device__ int    g_cell[NMAX];
__device__ int    g_rank[NMAX];
__device__ int    g_count[NCELLS];       // zero at load; k2 re-zeroes after use
__device__ int    g_start[NCELLS + 1];

// k1: zero out, build half-energy table (warp per entry), bin atoms.
__global__ __launch_bounds__(THREADS)
void setup_kernel(const float* __restrict__ xyz,
                  const float* __restrict__ cell_diag,
                  const float* __restrict__ W1,
                  const float* __restrict__ b1,
                  const float* __restrict__ W2,
                  const float* __restrict__ b2,
                  float* __restrict__ out,
                  int n) {
    int t = blockIdx.x * blockDim.x + threadIdx.x;
    if (t == 0) out[0] = 0.0f;

    if (t < n) {
        float x = xyz[3 * t + 0];
        float y = xyz[3 * t + 1];
        float z = xyz[3 * t + 2];
        float sx = (float)NCELL / cell_diag[0];
        float sy = (float)NCELL / cell_diag[1];
        float sz = (float)NCELL / cell_diag[2];
        int cx = min((int)(x * sx), NCELL - 1);
        int cy = min((int)(y * sy), NCELL - 1);
        int cz = min((int)(z * sz), NCELL - 1);
        int c = (cz * NCELL + cy) * NCELL + cx;
        g_tmp[t]  = make_float4(x, y, z, 0.0f);
        g_cell[t] = c;
        g_rank[t] = atomicAdd(&g_count[c], 1);
    }

    int warp = t >> 5;
    int lane = t & 31;
    if (warp <= TBL) {
        float r2 = (CUTOFF_SQ / (float)TBL) * (float)warp;
        float r  = sqrtf(r2);
        float v  = W2[lane] * tanhf(fmaf(r, W1[lane], b1[lane]));
        #pragma unroll
        for (int off = 16; off > 0; off >>= 1)
            v += __shfl_xor_sync(0xFFFFFFFFu, v, off);
        if (lane == 0) g_tbl[warp] = 0.5f * (v + b2[0]);
    }
}

// k2: exclusive scan of cell counts, then zero counts for the next replay.
__global__ void scan_kernel() {
    __shared__ int s_cnt[NCELLS];
    int t = threadIdx.x;
    if (t < NCELLS) s_cnt[t] = g_count[t];
    __syncthreads();
    if (t == 0) {
        int run = 0;
        #pragma unroll 5
        for (int c = 0; c < NCELLS; c++) {
            g_start[c] = run;
            run += s_cnt[c];
        }
        g_start[NCELLS] = run;
    }
    if (t < NCELLS) g_count[t] = 0;   // deterministic for next call
}

// k3: scatter atoms into cell-sorted order, pack cell id into .w.
__global__ __launch_bounds__(THREADS)
void scatter_kernel(int n) {
    int t = blockIdx.x * blockDim.x + threadIdx.x;
    if (t < n) {
        int c = g_cell[t];
        float4 p = g_tmp[t];
        p.w = __int_as_float(c);
        g_sorted[g_start[c] + g_rank[t]] = p;
    }
}

// k4: one warp per (i-atom, dz-plane). Lanes stride over the contiguous
// x-spans of the 3 neighbor (cy,cz) rows. Branch-free table body.
__global__ __launch_bounds__(THREADS)
void pair_energy_kernel(const float* __restrict__ cell_diag,
                        float* __restrict__ out,
                        int n) {
    __shared__ int   s_start[NCELLS + 1];
    __shared__ float warp_sums[THREADS / 32];

    const int tid = threadIdx.x;
    for (int s = tid; s <= NCELLS; s += THREADS) s_start[s] = g_start[s];
    __syncthreads();

    const int gw = (blockIdx.x * THREADS + tid) >> 5;
    const int lane = tid & 31;
    const int i = gw / 3;
    const int dz = gw % 3 - 1;

    const float Lx = cell_diag[0], Ly = cell_diag[1], Lz = cell_diag[2];
    const float iLx = 1.0f / Lx, iLy = 1.0f / Ly, iLz = 1.0f / Lz;
    const float invDr2 = (float)TBL / CUTOFF_SQ;
    const float r2clamp = CUTOFF_SQ * (1.0f - 1.0f / (float)TBL);

    float acc = 0.0f;

    if (i < n) {
        const float4 pi = g_sorted[i];
        const int ci = __float_as_int(pi.w);
        const int cx = ci % NCELL;
        const int cy = (ci / NCELL) % NCELL;
        const int cz = ci / (NCELL * NCELL);

        int czn = cz + dz;
        if (czn < 0) czn += NCELL;
        if (czn >= NCELL) czn -= NCELL;

        #pragma unroll
        for (int dy = -1; dy <= 1; dy++) {
            int cyn = cy + dy;
            if (cyn < 0) cyn += NCELL;
            if (cyn >= NCELL) cyn -= NCELL;
            int base = (czn * NCELL + cyn) * NCELL;

            int s0, e0, s1, e1;
            if (cx >= 1 && cx <= NCELL - 2) {
                s0 = s_start[base + cx - 1]; e0 = s_start[base + cx + 2];
                s1 = 0; e1 = 0;
            } else if (cx == 0) {
                s0 = s_start[base];             e0 = s_start[base + 2];
                s1 = s_start[base + NCELL - 1]; e1 = s_start[base + NCELL];
            } else { // cx == NCELL-1
                s0 = s_start[base + NCELL - 2]; e0 = s_start[base + NCELL];
                s1 = s_start[base];             e1 = s_start[base + 1];
            }

            #pragma unroll
            for (int sp = 0; sp < 2; sp++) {
                int js = sp ? s1 : s0;
                int je = sp ? e1 : e0;
                for (int j = js + lane; j < je; j += 32) {
                    float4 pj = g_sorted[j];
                    float dx = pj.x - pi.x;
                    float dyy = pj.y - pi.y;
                    float dzz = pj.z - pi.z;

                    dx  = fmaf(rintf(dx  * iLx), -Lx, dx);
                    dyy = fmaf(rintf(dyy * iLy), -Ly, dyy);
                    dzz = fmaf(rintf(dzz * iLz), -Lz, dzz);

                    float r2 = fmaf(dx, dx, fmaf(dyy, dyy, dzz * dzz));

                    bool hit = (r2 < CUTOFF_SQ) && (r2 > 0.0f);

                    float tt = fminf(r2, r2clamp) * invDr2;
                    int k = (int)tt;
                    float f = tt - (float)k;
                    float e0v = g_tbl[k];
                    float e1v = g_tbl[k + 1];
                    float e = fmaf(f, e1v - e0v, e0v);

                    acc += hit ? e : 0.0f;
                }
            }
        }
    }

    #pragma unroll
    for (int off = 16; off > 0; off >>= 1)
        acc += __shfl_down_sync(0xFFFFFFFFu, acc, off);

    int wid = tid >> 5;
    if (lane == 0) warp_sums[wid] = acc;
    __syncthreads();

    if (wid == 0) {
        float v = (lane < THREADS / 32) ? warp_sums[lane] : 0.0f;
        #pragma unroll
        for (int off = 16; off > 0; off >>= 1)
            v += __shfl_down_sync(0xFFFFFFFFu, v, off);
        if (lane == 0) {
            atomicAdd(out, v);
        }
    }
}

extern "C" void kernel_launch(void* const* d_in, const int* in_sizes, int n_in,
                              void* d_out, int out_size) {
    const float* xyz       = (const float*)d_in[0];
    const float* cell_diag = (const float*)d_in[1];
    const float* W1        = (const float*)d_in[2];
    const float* b1        = (const float*)d_in[3];
    const float* W2        = (const float*)d_in[4];
    const float* b2        = (const float*)d_in[5];
    float* out = (float*)d_out;

    int n = in_sizes[0] / 3;

    long st = (long)(TBL + 1) * 32;
    if (st < n) st = n;
    int setup_blocks = (int)((st + THREADS - 1) / THREADS);
    setup_kernel<<<setup_blocks, THREADS>>>(xyz, cell_diag, W1, b1, W2, b2, out, n);

    scan_kernel<<<1, 128>>>();

    scatter_kernel<<<(n + THREADS - 1) / THREADS, THREADS>>>(n);

    long pw = (long)n * 3 * 32;
    int pair_blocks = (int)((pw + THREADS - 1) / THREADS);
    pair_energy_kernel<<<pair_blocks, THREADS>>>(cell_diag, out, n);
}